// round 4
// baseline (speedup 1.0000x reference)
#include <cuda_runtime.h>
#include <math.h>
#include <stdint.h>

#define N_NODES 10000
#define BATCH 4
#define MROWS (BATCH * N_NODES)   // 40000
#define E_MAX 160000

// ------------------------------------------------------------------
// Static device scratch (no allocation allowed in kernel_launch)
// ------------------------------------------------------------------
__device__ float g_bufA[(size_t)MROWS * 256];
__device__ float g_bufB[(size_t)MROWS * 256];
__device__ float g_bufC[(size_t)MROWS * 256];
__device__ int   g_counts[N_NODES];
__device__ int   g_off[N_NODES + 1];
__device__ int   g_cursor[N_NODES];
__device__ int   g_ssrc[E_MAX];
__device__ float g_scores[MROWS];
__device__ float g_r[BATCH * 256];
__device__ float g_xbar[BATCH * 256];

// ------------------------------------------------------------------
// Utility kernels
// ------------------------------------------------------------------
__global__ void zero_f_kernel(float* p, int n) {
    int i = blockIdx.x * blockDim.x + threadIdx.x;
    if (i < n) p[i] = 0.f;
}

__global__ void zero_counts_kernel() {
    int i = blockIdx.x * blockDim.x + threadIdx.x;
    if (i < N_NODES) g_counts[i] = 0;
}

__global__ void hist_kernel(const int* __restrict__ dst, int E) {
    for (int e = blockIdx.x * blockDim.x + threadIdx.x; e < E;
         e += gridDim.x * blockDim.x)
        atomicAdd(&g_counts[dst[e]], 1);
}

// single-block exclusive scan of g_counts -> g_off (N_NODES + total at end)
__global__ void scan_kernel() {
    __shared__ int ssum[1024];
    const int CH = 10;                    // 1024*10 >= 10000
    int t = threadIdx.x;
    int base_i = t * CH;
    int vals[CH];
    int local = 0;
#pragma unroll
    for (int i = 0; i < CH; i++) {
        int idx = base_i + i;
        int v = (idx < N_NODES) ? g_counts[idx] : 0;
        vals[i] = local;                  // exclusive prefix within chunk
        local += v;
    }
    ssum[t] = local;
    __syncthreads();
    for (int off = 1; off < 1024; off <<= 1) {
        int v = (t >= off) ? ssum[t - off] : 0;
        __syncthreads();
        ssum[t] += v;
        __syncthreads();
    }
    int pre = (t > 0) ? ssum[t - 1] : 0;
#pragma unroll
    for (int i = 0; i < CH; i++) {
        int idx = base_i + i;
        if (idx < N_NODES) g_off[idx] = pre + vals[i];
    }
    if (t == 1023) g_off[N_NODES] = ssum[1023];
}

__global__ void copy_off_kernel() {
    int i = blockIdx.x * blockDim.x + threadIdx.x;
    if (i < N_NODES) g_cursor[i] = g_off[i];
}

__global__ void scatter_kernel(const int* __restrict__ src,
                               const int* __restrict__ dst, int E) {
    for (int e = blockIdx.x * blockDim.x + threadIdx.x; e < E;
         e += gridDim.x * blockDim.x) {
        int p = atomicAdd(&g_cursor[dst[e]], 1);
        g_ssrc[p] = src[e];
    }
}

// ------------------------------------------------------------------
// CSR aggregation: out[b,d,:] = sum_{e: dst=d} in[b,src[e],:]
// blockDim.x == F, grid (N_NODES, BATCH)
// ------------------------------------------------------------------
__global__ void aggregate_kernel(const float* __restrict__ in,
                                 float* __restrict__ out, int F) {
    int node = blockIdx.x;
    int bt = blockIdx.y;
    int beg = g_off[node];
    int end = g_off[node + 1];
    const float* inb = in + (size_t)bt * N_NODES * F;
    float acc = 0.f;
    for (int j = beg; j < end; j++) {
        int s = g_ssrc[j];
        acc += inb[(size_t)s * F + threadIdx.x];
    }
    out[((size_t)bt * N_NODES + node) * F + threadIdx.x] = acc;
}

// ------------------------------------------------------------------
// Tiled SGEMM: C[M,N] = epi(A[M,K] @ B[K,N] + bias[N] (+ res[M,N]))
// BM=BN=64, BK=16, 256 threads, 4x4 per thread.
// Requires M%64==0, N%64==0, K%16==0 (true for all uses here).
// EPI: 0 none, 1 relu, 2 gelu(exact)
// ------------------------------------------------------------------
template <int EPI>
__global__ __launch_bounds__(256) void sgemm_kernel(
    const float* __restrict__ A, const float* __restrict__ B,
    const float* __restrict__ bias, const float* __restrict__ res,
    float* __restrict__ C, int M, int N, int K) {
    const int BM = 64, BN = 64, BK = 16;
    __shared__ __align__(16) float As[BK][BM + 4];
    __shared__ __align__(16) float Bs[BK][BN + 4];
    int tid = threadIdx.x;
    int bm = blockIdx.y * BM;
    int bn = blockIdx.x * BN;
    int arow = tid >> 2;           // 0..63
    int acol = (tid & 3) << 2;     // 0,4,8,12
    int brow = tid >> 4;           // 0..15
    int bcol = (tid & 15) << 2;    // 0..60
    int ty = tid >> 4;             // 0..15
    int tx = tid & 15;             // 0..15

    float acc[4][4];
#pragma unroll
    for (int i = 0; i < 4; i++)
#pragma unroll
        for (int j = 0; j < 4; j++) acc[i][j] = 0.f;

    const float* Aptr = A + (size_t)(bm + arow) * K + acol;
    const float* Bptr = B + (size_t)brow * N + bn + bcol;

    for (int k0 = 0; k0 < K; k0 += BK) {
        float4 av = *(const float4*)(Aptr + k0);
        float4 bv = *(const float4*)(Bptr + (size_t)k0 * N);
        As[acol + 0][arow] = av.x;
        As[acol + 1][arow] = av.y;
        As[acol + 2][arow] = av.z;
        As[acol + 3][arow] = av.w;
        *(float4*)(&Bs[brow][bcol]) = bv;
        __syncthreads();
#pragma unroll
        for (int k = 0; k < BK; k++) {
            float4 a4 = *(const float4*)(&As[k][ty << 2]);
            float4 b4 = *(const float4*)(&Bs[k][tx << 2]);
            float ar[4] = {a4.x, a4.y, a4.z, a4.w};
            float br[4] = {b4.x, b4.y, b4.z, b4.w};
#pragma unroll
            for (int i = 0; i < 4; i++)
#pragma unroll
                for (int j = 0; j < 4; j++)
                    acc[i][j] = fmaf(ar[i], br[j], acc[i][j]);
        }
        __syncthreads();
    }

#pragma unroll
    for (int i = 0; i < 4; i++) {
        int row = bm + (ty << 2) + i;
        size_t rowoff = (size_t)row * N;
#pragma unroll
        for (int j = 0; j < 4; j++) {
            int col = bn + (tx << 2) + j;
            float v = acc[i][j] + bias[col];
            if (res) v += res[rowoff + col];
            if (EPI == 1) v = fmaxf(v, 0.f);
            if (EPI == 2) v = 0.5f * v * (1.f + erff(v * 0.70710678118654752f));
            C[rowoff + col] = v;
        }
    }
}

// ------------------------------------------------------------------
// LayerNorm over D=256; optional broadcast-add of r[b,:] first.
// One warp per row; blockDim 256 (8 warps); grid MROWS/8.
// ------------------------------------------------------------------
__global__ void ln_kernel(const float* __restrict__ x, const float* __restrict__ r,
                          const float* __restrict__ g, const float* __restrict__ b,
                          float* __restrict__ out) {
    int row = blockIdx.x * 8 + (threadIdx.x >> 5);
    if (row >= MROWS) return;
    int lane = threadIdx.x & 31;
    int bt = row / N_NODES;
    const float* xr = x + (size_t)row * 256;
    float v[8];
    float s = 0.f;
#pragma unroll
    for (int i = 0; i < 8; i++) {
        int c = lane + (i << 5);
        float t = xr[c];
        if (r) t += r[bt * 256 + c];
        v[i] = t;
        s += t;
    }
#pragma unroll
    for (int o = 16; o > 0; o >>= 1) s += __shfl_xor_sync(0xffffffffu, s, o);
    float mu = s * (1.f / 256.f);
    float vs = 0.f;
#pragma unroll
    for (int i = 0; i < 8; i++) {
        float d = v[i] - mu;
        vs += d * d;
    }
#pragma unroll
    for (int o = 16; o > 0; o >>= 1) vs += __shfl_xor_sync(0xffffffffu, vs, o);
    float inv = rsqrtf(vs * (1.f / 256.f) + 1e-5f);
#pragma unroll
    for (int i = 0; i < 8; i++) {
        int c = lane + (i << 5);
        out[(size_t)row * 256 + c] = (v[i] - mu) * inv * g[c] + b[c];
    }
}

// ------------------------------------------------------------------
// Attention-pool helpers
// ------------------------------------------------------------------
// scores[row] = tanh(x[row,:] @ W(256x8)) . u(8) ; one warp per row
__global__ void attn_score_kernel(const float* __restrict__ x,
                                  const float* __restrict__ W,
                                  const float* __restrict__ u,
                                  float* __restrict__ sc) {
    int row = blockIdx.x * 8 + (threadIdx.x >> 5);
    if (row >= MROWS) return;
    int lane = threadIdx.x & 31;
    const float* xr = x + (size_t)row * 256;
    float acc[8] = {0, 0, 0, 0, 0, 0, 0, 0};
#pragma unroll
    for (int i = 0; i < 8; i++) {
        int k = lane + (i << 5);
        float xv = xr[k];
#pragma unroll
        for (int j = 0; j < 8; j++) acc[j] = fmaf(xv, W[k * 8 + j], acc[j]);
    }
#pragma unroll
    for (int j = 0; j < 8; j++)
#pragma unroll
        for (int o = 16; o > 0; o >>= 1)
            acc[j] += __shfl_xor_sync(0xffffffffu, acc[j], o);
    if (lane == 0) {
        float a = 0.f;
#pragma unroll
        for (int j = 0; j < 8; j++) a += tanhf(acc[j]) * u[j];
        sc[row] = a;
    }
}

// scores[row] = x[row,:] . r[b,:]
__global__ void dot_r_kernel(const float* __restrict__ x,
                             const float* __restrict__ r,
                             float* __restrict__ sc) {
    int row = blockIdx.x * 8 + (threadIdx.x >> 5);
    if (row >= MROWS) return;
    int lane = threadIdx.x & 31;
    int bt = row / N_NODES;
    const float* xr = x + (size_t)row * 256;
    const float* rb = r + bt * 256;
    float a = 0.f;
#pragma unroll
    for (int i = 0; i < 8; i++) {
        int k = lane + (i << 5);
        a = fmaf(xr[k], rb[k], a);
    }
#pragma unroll
    for (int o = 16; o > 0; o >>= 1) a += __shfl_xor_sync(0xffffffffu, a, o);
    if (lane == 0) sc[row] = a;
}

// in-place softmax over N_NODES per batch; grid = BATCH, block = 1024
__global__ void softmax_kernel(float* __restrict__ sc) {
    int bt = blockIdx.x;
    float* s = sc + (size_t)bt * N_NODES;
    __shared__ float red[32];
    int tid = threadIdx.x, lane = tid & 31, w = tid >> 5;

    float m = -1e30f;
    for (int n = tid; n < N_NODES; n += 1024) m = fmaxf(m, s[n]);
#pragma unroll
    for (int o = 16; o > 0; o >>= 1) m = fmaxf(m, __shfl_xor_sync(~0u, m, o));
    if (lane == 0) red[w] = m;
    __syncthreads();
    if (w == 0) {
        float t = red[lane];
#pragma unroll
        for (int o = 16; o > 0; o >>= 1) t = fmaxf(t, __shfl_xor_sync(~0u, t, o));
        red[0] = t;
    }
    __syncthreads();
    float bm = red[0];
    __syncthreads();

    float sum = 0.f;
    for (int n = tid; n < N_NODES; n += 1024) sum += expf(s[n] - bm);
#pragma unroll
    for (int o = 16; o > 0; o >>= 1) sum += __shfl_xor_sync(~0u, sum, o);
    if (lane == 0) red[w] = sum;
    __syncthreads();
    if (w == 0) {
        float t = red[lane];
#pragma unroll
        for (int o = 16; o > 0; o >>= 1) t += __shfl_xor_sync(~0u, t, o);
        red[0] = t;
    }
    __syncthreads();
    float inv = 1.f / red[0];
    for (int n = tid; n < N_NODES; n += 1024) s[n] = expf(s[n] - bm) * inv;
}

// r[b,:] += sum over chunk of weight[n] * x[b,n,:]; weight = alpha or scale
// grid (NCHUNK, BATCH), block 256 (one thread per feature)
__global__ void wsum_kernel(const float* __restrict__ x,
                            const float* __restrict__ alpha, float scale,
                            float* __restrict__ r) {
    int bt = blockIdx.y;
    int per = N_NODES / gridDim.x;
    int n0 = blockIdx.x * per;
    int n1 = n0 + per;
    const float* xb = x + (size_t)bt * N_NODES * 256;
    const float* ab = alpha ? alpha + (size_t)bt * N_NODES : nullptr;
    float acc = 0.f;
    for (int n = n0; n < n1; n++) {
        float wv = ab ? ab[n] : scale;
        acc = fmaf(wv, xb[(size_t)n * 256 + threadIdx.x], acc);
    }
    atomicAdd(&r[bt * 256 + threadIdx.x], acc);
}

// out[b,o] = xbar[b,:] . fcW[:,o] + fcb[o]
__global__ void fc_kernel(const float* __restrict__ xbar,
                          const float* __restrict__ W,
                          const float* __restrict__ b, float* __restrict__ out) {
    int t = threadIdx.x;
    if (t >= BATCH * 10) return;
    int bt = t / 10, o = t % 10;
    float a = b[o];
#pragma unroll 8
    for (int k = 0; k < 256; k++) a = fmaf(xbar[bt * 256 + k], W[k * 10 + o], a);
    out[t] = a;
}

// ------------------------------------------------------------------
// Orchestration
// ------------------------------------------------------------------
extern "C" void kernel_launch(void* const* d_in, const int* in_sizes, int n_in,
                              void* d_out, int out_size) {
    const float* x       = (const float*)d_in[0];
    const int*   src     = (const int*)d_in[1];
    const int*   dst     = (const int*)d_in[2];
    const float* W_conv0 = (const float*)d_in[3];
    const float* b_conv0 = (const float*)d_in[4];
    const float* W_convs = (const float*)d_in[5];
    const float* b_convs = (const float*)d_in[6];
    const float* mW1 = (const float*)d_in[7];
    const float* mb1 = (const float*)d_in[8];
    const float* mW2 = (const float*)d_in[9];
    const float* mb2 = (const float*)d_in[10];
    const float* mW3 = (const float*)d_in[11];
    const float* mb3 = (const float*)d_in[12];
    const float* ln1_g = (const float*)d_in[13];
    const float* ln1_b = (const float*)d_in[14];
    const float* ln2_g = (const float*)d_in[15];
    const float* ln2_b = (const float*)d_in[16];
    const float* attnW = (const float*)d_in[17];
    const float* attnu = (const float*)d_in[18];
    const float* fW1 = (const float*)d_in[19];
    const float* fb1 = (const float*)d_in[20];
    const float* fW2 = (const float*)d_in[21];
    const float* fb2 = (const float*)d_in[22];
    const float* fcW = (const float*)d_in[23];
    const float* fcb = (const float*)d_in[24];
    int E = in_sizes[1];
    float* out = (float*)d_out;

    float *bufA, *bufB, *bufC, *scores, *rvec, *xbar;
    cudaGetSymbolAddress((void**)&bufA, g_bufA);
    cudaGetSymbolAddress((void**)&bufB, g_bufB);
    cudaGetSymbolAddress((void**)&bufC, g_bufC);
    cudaGetSymbolAddress((void**)&scores, g_scores);
    cudaGetSymbolAddress((void**)&rvec, g_r);
    cudaGetSymbolAddress((void**)&xbar, g_xbar);

    // ---- CSR build (amortized over 16 aggregations) ----
    zero_counts_kernel<<<(N_NODES + 255) / 256, 256>>>();
    hist_kernel<<<256, 256>>>(dst, E);
    scan_kernel<<<1, 1024>>>();
    copy_off_kernel<<<(N_NODES + 255) / 256, 256>>>();
    scatter_kernel<<<256, 256>>>(src, dst, E);

    // ---- GCN layer 0: aggregate(x) then GEMM(128->256) + bias + gelu ----
    aggregate_kernel<<<dim3(N_NODES, BATCH), 128>>>(x, bufA, 128);
    sgemm_kernel<2><<<dim3(256 / 64, MROWS / 64), 256>>>(
        bufA, W_conv0, b_conv0, nullptr, bufB, MROWS, 256, 128);

    // ---- GCN layers 1..3 ----
    for (int i = 0; i < 3; i++) {
        aggregate_kernel<<<dim3(N_NODES, BATCH), 256>>>(bufB, bufA, 256);
        sgemm_kernel<2><<<dim3(4, MROWS / 64), 256>>>(
            bufA, W_convs + (size_t)i * 256 * 256, b_convs + i * 256, nullptr,
            bufB, MROWS, 256, 256);
    }

    // ---- MLP ----
    sgemm_kernel<1><<<dim3(2, MROWS / 64), 256>>>(bufB, mW1, mb1, nullptr, bufA,
                                                  MROWS, 128, 256);
    sgemm_kernel<1><<<dim3(1, MROWS / 64), 256>>>(bufA, mW2, mb2, nullptr, bufC,
                                                  MROWS, 64, 128);
    sgemm_kernel<0><<<dim3(4, MROWS / 64), 256>>>(bufC, mW3, mb3, nullptr, bufB,
                                                  MROWS, 256, 64);

    // ---- 2 transformer-style blocks (x lives in bufB) ----
    for (int i = 0; i < 2; i++) {
        // attention pool -> rvec
        attn_score_kernel<<<MROWS / 8, 256>>>(bufB, attnW + (size_t)i * 256 * 8,
                                              attnu + i * 8, scores);
        softmax_kernel<<<BATCH, 1024>>>(scores);
        zero_f_kernel<<<1, 1024>>>(rvec, BATCH * 256);
        wsum_kernel<<<dim3(40, BATCH), 256>>>(bufB, scores, 0.f, rvec);
        for (int it = 0; it < 3; it++) {
            dot_r_kernel<<<MROWS / 8, 256>>>(bufB, rvec, scores);
            softmax_kernel<<<BATCH, 1024>>>(scores);
            zero_f_kernel<<<1, 1024>>>(rvec, BATCH * 256);
            wsum_kernel<<<dim3(40, BATCH), 256>>>(bufB, scores, 0.f, rvec);
        }
        // x = LN1(x + r)
        ln_kernel<<<MROWS / 8, 256>>>(bufB, rvec, ln1_g + i * 256,
                                      ln1_b + i * 256, bufA);
        // FFN: h = relu(x@fW1+fb1)@fW2+fb2 ; x = LN2(x + h)
        sgemm_kernel<1><<<dim3(4, MROWS / 64), 256>>>(
            bufA, fW1 + (size_t)i * 256 * 256, fb1 + i * 256, nullptr, bufC,
            MROWS, 256, 256);
        sgemm_kernel<0><<<dim3(4, MROWS / 64), 256>>>(
            bufC, fW2 + (size_t)i * 256 * 256, fb2 + i * 256, bufA, bufB,
            MROWS, 256, 256);
        ln_kernel<<<MROWS / 8, 256>>>(bufB, nullptr, ln2_g + i * 256,
                                      ln2_b + i * 256, bufB);
    }

    // ---- final: out = mean_n(x) @ fcW + fcb ----
    zero_f_kernel<<<1, 1024>>>(xbar, BATCH * 256);
    wsum_kernel<<<dim3(40, BATCH), 256>>>(bufB, nullptr, 1.f / N_NODES, xbar);
    fc_kernel<<<1, 64>>>(xbar, fcW, fcb, out);
}

// round 6
// speedup vs baseline: 1.2862x; 1.2862x over previous
#include <cuda_runtime.h>
#include <cuda_fp16.h>
#include <math.h>
#include <stdint.h>

#define N_NODES 10000
#define BATCH 4
#define MROWS (BATCH * N_NODES)     // 40000
#define MPAD  40064                 // 313 * 128
#define E_MAX 160000

// ------------------------------------------------------------------
// Static device scratch
// ------------------------------------------------------------------
__device__ __align__(16) float g_bufA[(size_t)MPAD * 256];
__device__ __align__(16) float g_bufB[(size_t)MPAD * 256];
__device__ __align__(16) float g_bufC[(size_t)MPAD * 256];
__device__ __align__(16) __half g_wHi[560000];
__device__ __align__(16) __half g_wLo[560000];
__device__ int   g_counts[N_NODES];
__device__ int   g_off[N_NODES + 1];
__device__ int   g_cursor[N_NODES];
__device__ int   g_ssrc[E_MAX];
__device__ float g_scores[MROWS];
__device__ float g_r[BATCH * 256];
__device__ float g_xbar[BATCH * 256];

// Weight offsets (halves) in g_wHi / g_wLo, layout [N][K] (K-contiguous)
#define OFF_CONV0 0          // 256x128
#define OFF_CONVS 32768      // 3 x 256x256
#define OFF_MW1   229376     // 128x256
#define OFF_MW2   262144     // 64x128
#define OFF_MW3   270336     // 256x64
#define OFF_FW1   286720     // 2 x 256x256
#define OFF_FW2   417792     // 2 x 256x256

__device__ __forceinline__ uint32_t smem_u32(const void* p) {
    uint32_t a;
    asm("{ .reg .u64 t; cvta.to.shared.u64 t, %1; cvt.u32.u64 %0, t; }"
        : "=r"(a) : "l"(p));
    return a;
}

// ------------------------------------------------------------------
// CSR build
// ------------------------------------------------------------------
__global__ void zero_f_kernel(float* p, int n) {
    int i = blockIdx.x * blockDim.x + threadIdx.x;
    if (i < n) p[i] = 0.f;
}

__global__ void zero_counts_kernel() {
    int i = blockIdx.x * blockDim.x + threadIdx.x;
    if (i < N_NODES) g_counts[i] = 0;
}

__global__ void hist_kernel(const int* __restrict__ dst, int E) {
    for (int e = blockIdx.x * blockDim.x + threadIdx.x; e < E;
         e += gridDim.x * blockDim.x)
        atomicAdd(&g_counts[dst[e]], 1);
}

__global__ void scan_kernel() {
    __shared__ int ssum[1024];
    const int CH = 10;
    int t = threadIdx.x;
    int base_i = t * CH;
    int vals[CH];
    int local = 0;
#pragma unroll
    for (int i = 0; i < CH; i++) {
        int idx = base_i + i;
        int v = (idx < N_NODES) ? g_counts[idx] : 0;
        vals[i] = local;
        local += v;
    }
    ssum[t] = local;
    __syncthreads();
    for (int off = 1; off < 1024; off <<= 1) {
        int v = (t >= off) ? ssum[t - off] : 0;
        __syncthreads();
        ssum[t] += v;
        __syncthreads();
    }
    int pre = (t > 0) ? ssum[t - 1] : 0;
#pragma unroll
    for (int i = 0; i < CH; i++) {
        int idx = base_i + i;
        if (idx < N_NODES) g_off[idx] = pre + vals[i];
    }
    if (t == 1023) g_off[N_NODES] = ssum[1023];
}

__global__ void copy_off_kernel() {
    int i = blockIdx.x * blockDim.x + threadIdx.x;
    if (i < N_NODES) g_cursor[i] = g_off[i];
}

__global__ void scatter_kernel(const int* __restrict__ src,
                               const int* __restrict__ dst, int E) {
    for (int e = blockIdx.x * blockDim.x + threadIdx.x; e < E;
         e += gridDim.x * blockDim.x) {
        int p = atomicAdd(&g_cursor[dst[e]], 1);
        g_ssrc[p] = src[e];
    }
}

// ------------------------------------------------------------------
// Weight split + transpose: W[K,N] fp32 -> hi/lo [N][K] fp16
// ------------------------------------------------------------------
__global__ void wsplit_kernel(const float* __restrict__ W, int K, int N,
                              __half* __restrict__ hi,
                              __half* __restrict__ lo) {
    int idx = blockIdx.x * blockDim.x + threadIdx.x;
    if (idx >= K * N) return;
    int k = idx / N, n = idx % N;
    float w = W[idx];
    __half h = __float2half_rn(w);
    hi[n * K + k] = h;
    lo[n * K + k] = __float2half_rn(w - __half2float(h));
}

// ------------------------------------------------------------------
// CSR aggregation: out[b,d,:] = sum_{e: dst=d} in[b,src[e],:]
// blockDim.x == F, grid (N_NODES, BATCH)
// ------------------------------------------------------------------
__global__ void aggregate_kernel(const float* __restrict__ in,
                                 float* __restrict__ out, int F) {
    int node = blockIdx.x;
    int bt = blockIdx.y;
    int beg = g_off[node];
    int end = g_off[node + 1];
    const float* inb = in + (size_t)bt * N_NODES * F;
    float acc = 0.f;
#pragma unroll 4
    for (int j = beg; j < end; j++) {
        int s = g_ssrc[j];
        acc += inb[(size_t)s * F + threadIdx.x];
    }
    out[((size_t)bt * N_NODES + node) * F + threadIdx.x] = acc;
}

// ------------------------------------------------------------------
// HMMA GEMM (mma.sync m16n8k16, fp16 hi/lo x3 for fp32 accuracy)
// C[M=MPAD, N] = epi(A[M,K] @ B^T + bias (+ res)); B stored [N][K] fp16 hi/lo
// Block: 256 thr, BM=128 x BN cols; K chunked by 64 through smem (swizzled).
// EPI: 0 none, 1 relu, 2 gelu(exact)
// ------------------------------------------------------------------
#define SWZ(o) ((o) ^ (((o) >> 3) & 0x70))

__device__ __forceinline__ void ldmx4(uint32_t* d, uint32_t addr) {
    asm volatile(
        "ldmatrix.sync.aligned.m8n8.x4.shared.b16 {%0,%1,%2,%3}, [%4];"
        : "=r"(d[0]), "=r"(d[1]), "=r"(d[2]), "=r"(d[3])
        : "r"(addr));
}

__device__ __forceinline__ void mma16816(float* c, const uint32_t* a,
                                         uint32_t b0, uint32_t b1) {
    asm volatile(
        "mma.sync.aligned.m16n8k16.row.col.f32.f16.f16.f32 "
        "{%0,%1,%2,%3}, {%4,%5,%6,%7}, {%8,%9}, {%0,%1,%2,%3};"
        : "+f"(c[0]), "+f"(c[1]), "+f"(c[2]), "+f"(c[3])
        : "r"(a[0]), "r"(a[1]), "r"(a[2]), "r"(a[3]), "r"(b0), "r"(b1));
}

template <int BN, int EPI, bool RES>
__global__ __launch_bounds__(256) void hmma_gemm(
    const float* __restrict__ A, int K, int N, const __half* __restrict__ Bhi,
    const __half* __restrict__ Blo, const float* __restrict__ bias,
    const float* __restrict__ res, float* __restrict__ C) {
    extern __shared__ char smem[];
    constexpr int KC = 64;
    constexpr int SA_HI = 0;                    // 128 x 64 fp16 = 16KB
    constexpr int SA_LO = 16384;
    constexpr int SB_HI = 32768;                // BN x 64 fp16
    constexpr int SB_LO = 32768 + BN * 128;
    constexpr int NWN = (BN == 128) ? 2 : 1;    // warps along N
    constexpr int WARPS_M = 8 / NWN;
    constexpr int WM = 128 / WARPS_M;           // 32 or 16
    constexpr int MB = WM / 16;                 // 2 or 1

    const int tid = threadIdx.x;
    const int wid = tid >> 5;
    const int lane = tid & 31;
    const int tileM = blockIdx.x * 128;
    const int bnG = blockIdx.y * BN;
    const uint32_t sb = smem_u32(smem);

    const int wmi = wid & (WARPS_M - 1);
    const int wni = wid / WARPS_M;

    // loader indices
    const int lr = tid >> 1;            // A row 0..127
    const int lcb = (tid & 1) * 32;     // A col base (fp32)
    const float* Arow = A + (size_t)(tileM + lr) * K + lcb;

    float acc[MB][8][4];
#pragma unroll
    for (int m = 0; m < MB; m++)
#pragma unroll
        for (int j = 0; j < 8; j++)
#pragma unroll
            for (int q = 0; q < 4; q++) acc[m][j][q] = 0.f;

    const int mat = lane >> 3, r8 = lane & 7;

    const int nchunks = K / KC;
    for (int c = 0; c < nchunks; c++) {
        if (c) __syncthreads();
        // ---- load A chunk, split into hi/lo fp16 ----
#pragma unroll
        for (int g = 0; g < 4; g++) {
            float4 v0 = *(const float4*)(Arow + c * KC + g * 8);
            float4 v1 = *(const float4*)(Arow + c * KC + g * 8 + 4);
            float f[8] = {v0.x, v0.y, v0.z, v0.w, v1.x, v1.y, v1.z, v1.w};
            __half hi[8], lo[8];
#pragma unroll
            for (int k = 0; k < 8; k++) {
                hi[k] = __float2half_rn(f[k]);
                lo[k] = __float2half_rn(f[k] - __half2float(hi[k]));
            }
            uint32_t off = lr * 128 + lcb * 2 + g * 16;
            uint32_t sw = SWZ(off);
            *(uint4*)(smem + SA_HI + sw) = *(uint4*)hi;
            *(uint4*)(smem + SA_LO + sw) = *(uint4*)lo;
        }
        // ---- load B hi/lo chunk (BN x 64 fp16 each) ----
#pragma unroll
        for (int it = 0; it < BN / 32; it++) {
            int e = tid + it * 256;
            int n = e >> 3, i = e & 7;
            size_t go = (size_t)(bnG + n) * K + c * KC + i * 8;
            uint4 vh = *(const uint4*)(Bhi + go);
            uint4 vl = *(const uint4*)(Blo + go);
            uint32_t off = n * 128 + i * 16;
            uint32_t sw = SWZ(off);
            *(uint4*)(smem + SB_HI + sw) = vh;
            *(uint4*)(smem + SB_LO + sw) = vl;
        }
        __syncthreads();

        // ---- MMA over 4 k16 steps ----
#pragma unroll
        for (int q = 0; q < 4; q++) {
            uint32_t ah[MB][4], al[MB][4];
#pragma unroll
            for (int m = 0; m < MB; m++) {
                int row = wmi * WM + m * 16 + (mat & 1) * 8 + r8;
                uint32_t off = row * 128 + q * 32 + (mat >> 1) * 16;
                uint32_t sw = SWZ(off);
                ldmx4(ah[m], sb + SA_HI + sw);
                ldmx4(al[m], sb + SA_LO + sw);
            }
#pragma unroll
            for (int h2 = 0; h2 < 2; h2++) {
                uint32_t bh[2][4], bl[2][4];
#pragma unroll
                for (int p = 0; p < 2; p++) {
                    int nb16 = h2 * 2 + p;
                    int n = wni * 64 + nb16 * 16 + (mat & 1) * 8 + r8;
                    uint32_t off = n * 128 + q * 32 + (mat >> 1) * 16;
                    uint32_t sw = SWZ(off);
                    ldmx4(bh[p], sb + SB_HI + sw);
                    ldmx4(bl[p], sb + SB_LO + sw);
                }
#pragma unroll
                for (int m = 0; m < MB; m++)
#pragma unroll
                    for (int p = 0; p < 2; p++)
#pragma unroll
                        for (int hn = 0; hn < 2; hn++) {
                            int j = (h2 * 2 + p) * 2 + hn;
                            mma16816(acc[m][j], ah[m], bh[p][hn],
                                     bh[p][2 + hn]);
                            mma16816(acc[m][j], ah[m], bl[p][hn],
                                     bl[p][2 + hn]);
                            mma16816(acc[m][j], al[m], bh[p][hn],
                                     bh[p][2 + hn]);
                        }
            }
        }
    }

    // ---- epilogue ----
#pragma unroll
    for (int m = 0; m < MB; m++) {
#pragma unroll
        for (int j = 0; j < 8; j++) {
            int col = bnG + wni * 64 + j * 8 + (lane & 3) * 2;
            float b0 = bias[col], b1 = bias[col + 1];
#pragma unroll
            for (int h = 0; h < 2; h++) {
                int row = tileM + wmi * WM + m * 16 + (lane >> 2) + h * 8;
                float v0 = acc[m][j][h * 2 + 0] + b0;
                float v1 = acc[m][j][h * 2 + 1] + b1;
                if (RES) {
                    v0 += res[(size_t)row * N + col];
                    v1 += res[(size_t)row * N + col + 1];
                }
                if (EPI == 1) {
                    v0 = fmaxf(v0, 0.f);
                    v1 = fmaxf(v1, 0.f);
                }
                if (EPI == 2) {
                    v0 = 0.5f * v0 * (1.f + erff(v0 * 0.70710678118654752f));
                    v1 = 0.5f * v1 * (1.f + erff(v1 * 0.70710678118654752f));
                }
                *(float2*)(C + (size_t)row * N + col) = make_float2(v0, v1);
            }
        }
    }
}

// ------------------------------------------------------------------
// LayerNorm over D=256; optional broadcast-add of r[b,:]
// ------------------------------------------------------------------
__global__ void ln_kernel(const float* __restrict__ x,
                          const float* __restrict__ r,
                          const float* __restrict__ g,
                          const float* __restrict__ b,
                          float* __restrict__ out) {
    int row = blockIdx.x * 8 + (threadIdx.x >> 5);
    if (row >= MROWS) return;
    int lane = threadIdx.x & 31;
    int bt = row / N_NODES;
    const float* xr = x + (size_t)row * 256;
    float v[8];
    float s = 0.f;
#pragma unroll
    for (int i = 0; i < 8; i++) {
        int c = lane + (i << 5);
        float t = xr[c];
        if (r) t += r[bt * 256 + c];
        v[i] = t;
        s += t;
    }
#pragma unroll
    for (int o = 16; o > 0; o >>= 1) s += __shfl_xor_sync(0xffffffffu, s, o);
    float mu = s * (1.f / 256.f);
    float vs = 0.f;
#pragma unroll
    for (int i = 0; i < 8; i++) {
        float d = v[i] - mu;
        vs += d * d;
    }
#pragma unroll
    for (int o = 16; o > 0; o >>= 1) vs += __shfl_xor_sync(0xffffffffu, vs, o);
    float inv = rsqrtf(vs * (1.f / 256.f) + 1e-5f);
#pragma unroll
    for (int i = 0; i < 8; i++) {
        int c = lane + (i << 5);
        out[(size_t)row * 256 + c] = (v[i] - mu) * inv * g[c] + b[c];
    }
}

// ------------------------------------------------------------------
// Attention-pool helpers
// ------------------------------------------------------------------
__global__ void attn_score_kernel(const float* __restrict__ x,
                                  const float* __restrict__ W,
                                  const float* __restrict__ u,
                                  float* __restrict__ sc) {
    int row = blockIdx.x * 8 + (threadIdx.x >> 5);
    if (row >= MROWS) return;
    int lane = threadIdx.x & 31;
    const float* xr = x + (size_t)row * 256;
    float acc[8] = {0, 0, 0, 0, 0, 0, 0, 0};
#pragma unroll
    for (int i = 0; i < 8; i++) {
        int k = lane + (i << 5);
        float xv = xr[k];
#pragma unroll
        for (int j = 0; j < 8; j++) acc[j] = fmaf(xv, W[k * 8 + j], acc[j]);
    }
#pragma unroll
    for (int j = 0; j < 8; j++)
#pragma unroll
        for (int o = 16; o > 0; o >>= 1)
            acc[j] += __shfl_xor_sync(0xffffffffu, acc[j], o);
    if (lane == 0) {
        float a = 0.f;
#pragma unroll
        for (int j = 0; j < 8; j++) a += tanhf(acc[j]) * u[j];
        sc[row] = a;
    }
}

__global__ void dot_r_kernel(const float* __restrict__ x,
                             const float* __restrict__ r,
                             float* __restrict__ sc) {
    int row = blockIdx.x * 8 + (threadIdx.x >> 5);
    if (row >= MROWS) return;
    int lane = threadIdx.x & 31;
    int bt = row / N_NODES;
    const float* xr = x + (size_t)row * 256;
    const float* rb = r + bt * 256;
    float a = 0.f;
#pragma unroll
    for (int i = 0; i < 8; i++) {
        int k = lane + (i << 5);
        a = fmaf(xr[k], rb[k], a);
    }
#pragma unroll
    for (int o = 16; o > 0; o >>= 1) a += __shfl_xor_sync(0xffffffffu, a, o);
    if (lane == 0) sc[row] = a;
}

__global__ void softmax_kernel(float* __restrict__ sc) {
    int bt = blockIdx.x;
    float* s = sc + (size_t)bt * N_NODES;
    __shared__ float red[32];
    int tid = threadIdx.x, lane = tid & 31, w = tid >> 5;

    float m = -1e30f;
    for (int n = tid; n < N_NODES; n += 1024) m = fmaxf(m, s[n]);
#pragma unroll
    for (int o = 16; o > 0; o >>= 1) m = fmaxf(m, __shfl_xor_sync(~0u, m, o));
    if (lane == 0) red[w] = m;
    __syncthreads();
    if (w == 0) {
        float t = red[lane];
#pragma unroll
        for (int o = 16; o > 0; o >>= 1)
            t = fmaxf(t, __shfl_xor_sync(~0u, t, o));
        red[0] = t;
    }
    __syncthreads();
    float bm = red[0];
    __syncthreads();

    float sum = 0.f;
    for (int n = tid; n < N_NODES; n += 1024) sum += expf(s[n] - bm);
#pragma unroll
    for (int o = 16; o > 0; o >>= 1) sum += __shfl_xor_sync(~0u, sum, o);
    if (lane == 0) red[w] = sum;
    __syncthreads();
    if (w == 0) {
        float t = red[lane];
#pragma unroll
        for (int o = 16; o > 0; o >>= 1) t += __shfl_xor_sync(~0u, t, o);
        red[0] = t;
    }
    __syncthreads();
    float inv = 1.f / red[0];
    for (int n = tid; n < N_NODES; n += 1024) s[n] = expf(s[n] - bm) * inv;
}

__global__ void wsum_kernel(const float* __restrict__ x,
                            const float* __restrict__ alpha, float scale,
                            float* __restrict__ r) {
    int bt = blockIdx.y;
    int per = N_NODES / gridDim.x;
    int n0 = blockIdx.x * per;
    int n1 = n0 + per;
    const float* xb = x + (size_t)bt * N_NODES * 256;
    const float* ab = alpha ? alpha + (size_t)bt * N_NODES : nullptr;
    float acc = 0.f;
    for (int n = n0; n < n1; n++) {
        float wv = ab ? ab[n] : scale;
        acc = fmaf(wv, xb[(size_t)n * 256 + threadIdx.x], acc);
    }
    atomicAdd(&r[bt * 256 + threadIdx.x], acc);
}

__global__ void fc_kernel(const float* __restrict__ xbar,
                          const float* __restrict__ W,
                          const float* __restrict__ b,
                          float* __restrict__ out) {
    int t = threadIdx.x;
    if (t >= BATCH * 10) return;
    int bt = t / 10, o = t % 10;
    float a = b[o];
#pragma unroll 8
    for (int k = 0; k < 256; k++) a = fmaf(xbar[bt * 256 + k], W[k * 10 + o], a);
    out[t] = a;
}

// ------------------------------------------------------------------
// Orchestration
// ------------------------------------------------------------------
extern "C" void kernel_launch(void* const* d_in, const int* in_sizes, int n_in,
                              void* d_out, int out_size) {
    const float* x       = (const float*)d_in[0];
    const int*   src     = (const int*)d_in[1];
    const int*   dst     = (const int*)d_in[2];
    const float* W_conv0 = (const float*)d_in[3];
    const float* b_conv0 = (const float*)d_in[4];
    const float* W_convs = (const float*)d_in[5];
    const float* b_convs = (const float*)d_in[6];
    const float* mW1 = (const float*)d_in[7];
    const float* mb1 = (const float*)d_in[8];
    const float* mW2 = (const float*)d_in[9];
    const float* mb2 = (const float*)d_in[10];
    const float* mW3 = (const float*)d_in[11];
    const float* mb3 = (const float*)d_in[12];
    const float* ln1_g = (const float*)d_in[13];
    const float* ln1_b = (const float*)d_in[14];
    const float* ln2_g = (const float*)d_in[15];
    const float* ln2_b = (const float*)d_in[16];
    const float* attnW = (const float*)d_in[17];
    const float* attnu = (const float*)d_in[18];
    const float* fW1 = (const float*)d_in[19];
    const float* fb1 = (const float*)d_in[20];
    const float* fW2 = (const float*)d_in[21];
    const float* fb2 = (const float*)d_in[22];
    const float* fcW = (const float*)d_in[23];
    const float* fcb = (const float*)d_in[24];
    int E = in_sizes[1];
    float* out = (float*)d_out;

    float *bufA, *bufB, *bufC, *scores, *rvec, *xbar;
    __half *wHi, *wLo;
    cudaGetSymbolAddress((void**)&bufA, g_bufA);
    cudaGetSymbolAddress((void**)&bufB, g_bufB);
    cudaGetSymbolAddress((void**)&bufC, g_bufC);
    cudaGetSymbolAddress((void**)&wHi, g_wHi);
    cudaGetSymbolAddress((void**)&wLo, g_wLo);
    cudaGetSymbolAddress((void**)&scores, g_scores);
    cudaGetSymbolAddress((void**)&rvec, g_r);
    cudaGetSymbolAddress((void**)&xbar, g_xbar);

    const int SM128 = 32768 + 128 * 256;  // 65536
    const int SM64 = 32768 + 64 * 256;    // 49152
    cudaFuncSetAttribute(hmma_gemm<128, 2, false>,
                         cudaFuncAttributeMaxDynamicSharedMemorySize, SM128);
    cudaFuncSetAttribute(hmma_gemm<128, 1, false>,
                         cudaFuncAttributeMaxDynamicSharedMemorySize, SM128);
    cudaFuncSetAttribute(hmma_gemm<128, 0, false>,
                         cudaFuncAttributeMaxDynamicSharedMemorySize, SM128);
    cudaFuncSetAttribute(hmma_gemm<128, 0, true>,
                         cudaFuncAttributeMaxDynamicSharedMemorySize, SM128);
    cudaFuncSetAttribute(hmma_gemm<64, 1, false>,
                         cudaFuncAttributeMaxDynamicSharedMemorySize, SM64);

    const int TILES = MPAD / 128;  // 313

    // ---- CSR build ----
    zero_counts_kernel<<<(N_NODES + 255) / 256, 256>>>();
    hist_kernel<<<256, 256>>>(dst, E);
    scan_kernel<<<1, 1024>>>();
    copy_off_kernel<<<(N_NODES + 255) / 256, 256>>>();
    scatter_kernel<<<256, 256>>>(src, dst, E);

    // ---- weight split/transpose to fp16 hi/lo [N][K] ----
    wsplit_kernel<<<(128 * 256 + 255) / 256, 256>>>(W_conv0, 128, 256,
                                                    wHi + OFF_CONV0,
                                                    wLo + OFF_CONV0);
    for (int i = 0; i < 3; i++)
        wsplit_kernel<<<(256 * 256 + 255) / 256, 256>>>(
            W_convs + (size_t)i * 65536, 256, 256, wHi + OFF_CONVS + i * 65536,
            wLo + OFF_CONVS + i * 65536);
    wsplit_kernel<<<(256 * 128 + 255) / 256, 256>>>(mW1, 256, 128,
                                                    wHi + OFF_MW1,
                                                    wLo + OFF_MW1);
    wsplit_kernel<<<(128 * 64 + 255) / 256, 256>>>(mW2, 128, 64, wHi + OFF_MW2,
                                                   wLo + OFF_MW2);
    wsplit_kernel<<<(64 * 256 + 255) / 256, 256>>>(mW3, 64, 256, wHi + OFF_MW3,
                                                   wLo + OFF_MW3);
    for (int i = 0; i < 2; i++) {
        wsplit_kernel<<<(256 * 256 + 255) / 256, 256>>>(
            fW1 + (size_t)i * 65536, 256, 256, wHi + OFF_FW1 + i * 65536,
            wLo + OFF_FW1 + i * 65536);
        wsplit_kernel<<<(256 * 256 + 255) / 256, 256>>>(
            fW2 + (size_t)i * 65536, 256, 256, wHi + OFF_FW2 + i * 65536,
            wLo + OFF_FW2 + i * 65536);
    }

    // ---- GCN layer 0: aggregate(x) then GEMM(K=128,N=256)+gelu ----
    aggregate_kernel<<<dim3(N_NODES, BATCH), 128>>>(x, bufA, 128);
    hmma_gemm<128, 2, false><<<dim3(TILES, 2), 256, SM128>>>(
        bufA, 128, 256, wHi + OFF_CONV0, wLo + OFF_CONV0, b_conv0, nullptr,
        bufB);

    // ---- GCN layers 1..3 ----
    for (int i = 0; i < 3; i++) {
        aggregate_kernel<<<dim3(N_NODES, BATCH), 256>>>(bufB, bufA, 256);
        hmma_gemm<128, 2, false><<<dim3(TILES, 2), 256, SM128>>>(
            bufA, 256, 256, wHi + OFF_CONVS + i * 65536,
            wLo + OFF_CONVS + i * 65536, b_convs + i * 256, nullptr, bufB);
    }

    // ---- MLP: 256 -> 128 -> 64 -> 256 ----
    hmma_gemm<128, 1, false><<<dim3(TILES, 1), 256, SM128>>>(
        bufB, 256, 128, wHi + OFF_MW1, wLo + OFF_MW1, mb1, nullptr, bufA);
    hmma_gemm<64, 1, false><<<dim3(TILES, 1), 256, SM64>>>(
        bufA, 128, 64, wHi + OFF_MW2, wLo + OFF_MW2, mb2, nullptr, bufB);
    hmma_gemm<128, 0, false><<<dim3(TILES, 2), 256, SM128>>>(
        bufB, 64, 256, wHi + OFF_MW3, wLo + OFF_MW3, mb3, nullptr, bufA);

    // ---- 2 transformer-style blocks (x fp32 in bufA) ----
    for (int i = 0; i < 2; i++) {
        attn_score_kernel<<<MROWS / 8, 256>>>(bufA, attnW + (size_t)i * 256 * 8,
                                              attnu + i * 8, scores);
        softmax_kernel<<<BATCH, 1024>>>(scores);
        zero_f_kernel<<<1, 1024>>>(rvec, BATCH * 256);
        wsum_kernel<<<dim3(40, BATCH), 256>>>(bufA, scores, 0.f, rvec);
        for (int it = 0; it < 3; it++) {
            dot_r_kernel<<<MROWS / 8, 256>>>(bufA, rvec, scores);
            softmax_kernel<<<BATCH, 1024>>>(scores);
            zero_f_kernel<<<1, 1024>>>(rvec, BATCH * 256);
            wsum_kernel<<<dim3(40, BATCH), 256>>>(bufA, scores, 0.f, rvec);
        }
        // x = LN1(x + r) -> bufB
        ln_kernel<<<MROWS / 8, 256>>>(bufA, rvec, ln1_g + i * 256,
                                      ln1_b + i * 256, bufB);
        // h = relu(x@fW1+fb1) -> bufC
        hmma_gemm<128, 1, false><<<dim3(TILES, 2), 256, SM128>>>(
            bufC ? bufB : bufB, 256, 256, wHi + OFF_FW1 + i * 65536,
            wLo + OFF_FW1 + i * 65536, fb1 + i * 256, nullptr, bufC);
        // x = h@fW2+fb2 + residual(bufB) -> bufA, then LN2 in place
        hmma_gemm<128, 0, true><<<dim3(TILES, 2), 256, SM128>>>(
            bufC, 256, 256, wHi + OFF_FW2 + i * 65536,
            wLo + OFF_FW2 + i * 65536, fb2 + i * 256, bufB, bufA);
        ln_kernel<<<MROWS / 8, 256>>>(bufA, nullptr, ln2_g + i * 256,
                                      ln2_b + i * 256, bufA);
    }

    // ---- final: out = mean_n(x) @ fcW + fcb ----
    zero_f_kernel<<<1, 1024>>>(xbar, BATCH * 256);
    wsum_kernel<<<dim3(40, BATCH), 256>>>(bufA, nullptr, 1.f / N_NODES, xbar);
    fc_kernel<<<1, 64>>>(xbar, fcW, fcb, out);
}